// round 1
// baseline (speedup 1.0000x reference)
#include <cuda_runtime.h>

#define BB 16
#define LL 192
#define EE 128
#define TT 25
#define NI (LL - TT - 1)            // 166
#define OUT_L (TT + 1 + NI * LL)    // 31898
#define E4 (EE / 4)                 // 32 float4 per row
#define I_PER_BLK 8
#define GX ((NI + I_PER_BLK - 1) / I_PER_BLK)  // 21
#define TPB 512
#define LROWS_PER_PASS (TPB / E4)   // 16
#define NPASS (LL / LROWS_PER_PASS) // 12

// Precomputed softmax weight s0[b,l,e] (s1 = 1 - s0). 1.5 MB, L2-resident.
__device__ float g_s0[BB * LL * EE];

// ---------------------------------------------------------------------------
// Kernel 1: s0 = sigmoid(x*(W0-W1) + (b0-b1))   (2-way softmax collapsed)
// ---------------------------------------------------------------------------
__global__ void s0_kernel(const float* __restrict__ x,
                          const float* __restrict__ W,
                          const float* __restrict__ bv) {
    const int N4 = BB * LL * E4;  // 98304
    int n = blockIdx.x * blockDim.x + threadIdx.x;
    if (n >= N4) return;
    float dW = W[0] - W[1];
    float db = bv[0] - bv[1];
    float4 xv = reinterpret_cast<const float4*>(x)[n];
    float4 s;
    s.x = 1.0f / (1.0f + __expf(-(fmaf(xv.x, dW, db))));
    s.y = 1.0f / (1.0f + __expf(-(fmaf(xv.y, dW, db))));
    s.z = 1.0f / (1.0f + __expf(-(fmaf(xv.z, dW, db))));
    s.w = 1.0f / (1.0f + __expf(-(fmaf(xv.w, dW, db))));
    reinterpret_cast<float4*>(g_s0)[n] = s;
}

// ---------------------------------------------------------------------------
// Kernel 2: head copy out[b, 0:26, :] = x[b, 0:26, :]
// ---------------------------------------------------------------------------
__global__ void head_kernel(const float* __restrict__ x, float* __restrict__ out) {
    const int HEAD4 = BB * (TT + 1) * E4;  // 13312
    int n = blockIdx.x * blockDim.x + threadIdx.x;
    if (n >= HEAD4) return;
    int b = n / ((TT + 1) * E4);
    int r = n - b * ((TT + 1) * E4);
    float4 v = reinterpret_cast<const float4*>(x)[b * (LL * E4) + r];
    reinterpret_cast<float4*>(out)[(size_t)b * (OUT_L * E4) + r] = v;
}

// ---------------------------------------------------------------------------
// Kernel 3: blocks[b,i,l,e] = xp + s0*(xi - xp),  xi=x[b,i+26,e], xp=x[b,i+1,e]
// One CTA: batch b, 8 consecutive i. s0[b,:,:] (96 KB) staged in SMEM once.
// Warp writes one contiguous 512B output row -> fully coalesced streaming STG.
// ---------------------------------------------------------------------------
__global__ void __launch_bounds__(TPB, 2)
blocks_kernel(const float* __restrict__ x, float* __restrict__ out) {
    extern __shared__ float4 s0s[];  // LL*E4 = 6144 float4 = 96 KB

    const int b = blockIdx.y;

    // Stage s0[b] into SMEM
    const float4* s0g = reinterpret_cast<const float4*>(g_s0) + (size_t)b * (LL * E4);
    #pragma unroll
    for (int k = threadIdx.x; k < LL * E4; k += TPB) s0s[k] = s0g[k];
    __syncthreads();

    const int e4    = threadIdx.x & (E4 - 1);   // 0..31, contiguous within warp
    const int lbase = threadIdx.x >> 5;         // 0..15, constant within warp
    const float4* x4 = reinterpret_cast<const float4*>(x);
    float4* o4 = reinterpret_cast<float4*>(out);

    const int i0 = blockIdx.x * I_PER_BLK;
    const int iend = min(i0 + I_PER_BLK, NI);

    for (int i = i0; i < iend; i++) {
        // xi = x[b, i+T+1, :], xp = x[b, i+1, :] — fixed per thread across l-loop
        float4 xi = x4[(b * LL + i + TT + 1) * E4 + e4];
        float4 xp = x4[(b * LL + i + 1) * E4 + e4];
        float4 d;
        d.x = xi.x - xp.x; d.y = xi.y - xp.y;
        d.z = xi.z - xp.z; d.w = xi.w - xp.w;

        size_t obase = ((size_t)b * OUT_L + (TT + 1) + (size_t)i * LL) * E4;

        #pragma unroll
        for (int p = 0; p < NPASS; p++) {
            int l = lbase + p * LROWS_PER_PASS;
            float4 s = s0s[l * E4 + e4];
            float4 o;
            o.x = fmaf(s.x, d.x, xp.x);
            o.y = fmaf(s.y, d.y, xp.y);
            o.z = fmaf(s.z, d.z, xp.z);
            o.w = fmaf(s.w, d.w, xp.w);
            // write-once output: streaming store, evict-first in L2
            __stcs(o4 + obase + (size_t)l * E4 + e4, o);
        }
    }
}

// ---------------------------------------------------------------------------
extern "C" void kernel_launch(void* const* d_in, const int* in_sizes, int n_in,
                              void* d_out, int out_size) {
    const float* x  = (const float*)d_in[0];  // (16,192,128) f32
    const float* W  = (const float*)d_in[1];  // (2,1) f32
    const float* bv = (const float*)d_in[2];  // (2,) f32
    float* out = (float*)d_out;               // (16,31898,128) f32

    const int N4 = BB * LL * E4;
    s0_kernel<<<(N4 + 255) / 256, 256>>>(x, W, bv);

    const int HEAD4 = BB * (TT + 1) * E4;
    head_kernel<<<(HEAD4 + 255) / 256, 256>>>(x, out);

    const int smem = LL * E4 * (int)sizeof(float4);  // 98304 B
    cudaFuncSetAttribute(blocks_kernel,
                         cudaFuncAttributeMaxDynamicSharedMemorySize, smem);
    dim3 grid(GX, BB);
    blocks_kernel<<<grid, TPB, smem>>>(x, out);
}

// round 2
// speedup vs baseline: 1.0869x; 1.0869x over previous
#include <cuda_runtime.h>

#define BB 16
#define LL 192
#define EE 128
#define TT 25
#define NI (LL - TT - 1)            // 166
#define OUT_L (TT + 1 + NI * LL)    // 31898
#define E4 (EE / 4)                 // 32 float4 per row
#define I_PER_BLK 10
#define GX ((NI + I_PER_BLK - 1) / I_PER_BLK)  // 17 -> wait: 166/10 = 16.6 -> 17
#define TPB 512
#define LROWS_PER_PASS (TPB / E4)   // 16
#define NPASS (LL / LROWS_PER_PASS) // 12

// ---------------------------------------------------------------------------
// Fused kernel:
//   - each CTA computes s0[b,:,:] = sigmoid(x[b]*(W0-W1) + (b0-b1)) into SMEM
//     (2-way softmax collapsed to sigmoid; s1 = 1-s0)
//   - blockIdx.x==0 CTAs also copy the head rows out[b,0:26,:] = x[b,0:26,:]
//   - main loop: blocks[b,i,l,e] = xp + s0[b,l,e]*(xi-xp),
//       xi = x[b, i+T+1, e], xp = x[b, i+1, e]
//   Warp writes one contiguous 512B output row -> coalesced streaming STG.
// ---------------------------------------------------------------------------
__global__ void __launch_bounds__(TPB, 2)
fused_kernel(const float* __restrict__ x,
             const float* __restrict__ W,
             const float* __restrict__ bv,
             float* __restrict__ out) {
    extern __shared__ float4 s0s[];  // LL*E4 = 6144 float4 = 96 KB

    const int b = blockIdx.y;
    const float dW = W[0] - W[1];
    const float db = bv[0] - bv[1];

    const float4* xb = reinterpret_cast<const float4*>(x) + b * (LL * E4);
    float4* o4 = reinterpret_cast<float4*>(out);

    // --- compute s0[b] into SMEM (12 float4 per thread) ---
    #pragma unroll
    for (int k = threadIdx.x; k < LL * E4; k += TPB) {
        float4 xv = xb[k];
        float4 s;
        s.x = 1.0f / (1.0f + __expf(-fmaf(xv.x, dW, db)));
        s.y = 1.0f / (1.0f + __expf(-fmaf(xv.y, dW, db)));
        s.z = 1.0f / (1.0f + __expf(-fmaf(xv.z, dW, db)));
        s.w = 1.0f / (1.0f + __expf(-fmaf(xv.w, dW, db)));
        s0s[k] = s;
    }

    // --- head copy (tiny: 832 float4), done by the x==0 CTA of each batch ---
    if (blockIdx.x == 0) {
        const size_t ob = (size_t)b * (OUT_L * E4);
        #pragma unroll
        for (int k = threadIdx.x; k < (TT + 1) * E4; k += TPB)
            __stcs(o4 + ob + k, xb[k]);
    }
    __syncthreads();

    const int e4    = threadIdx.x & (E4 - 1);   // 0..31, contiguous within warp
    const int lbase = threadIdx.x >> 5;         // 0..15, constant within warp

    const int i0 = blockIdx.x * I_PER_BLK;
    const int iend = min(i0 + I_PER_BLK, NI);

    for (int i = i0; i < iend; i++) {
        // xi = x[b, i+T+1, :], xp = x[b, i+1, :] — fixed per thread across l
        float4 xi = xb[(i + TT + 1) * E4 + e4];
        float4 xp = xb[(i + 1) * E4 + e4];
        float4 d;
        d.x = xi.x - xp.x; d.y = xi.y - xp.y;
        d.z = xi.z - xp.z; d.w = xi.w - xp.w;

        size_t obase = ((size_t)b * OUT_L + (TT + 1) + (size_t)i * LL) * E4;

        #pragma unroll
        for (int p = 0; p < NPASS; p++) {
            int l = lbase + p * LROWS_PER_PASS;
            float4 s = s0s[l * E4 + e4];
            float4 o;
            o.x = fmaf(s.x, d.x, xp.x);
            o.y = fmaf(s.y, d.y, xp.y);
            o.z = fmaf(s.z, d.z, xp.z);
            o.w = fmaf(s.w, d.w, xp.w);
            // write-once output: streaming store, evict-first in L2
            __stcs(o4 + obase + (size_t)l * E4 + e4, o);
        }
    }
}

// ---------------------------------------------------------------------------
extern "C" void kernel_launch(void* const* d_in, const int* in_sizes, int n_in,
                              void* d_out, int out_size) {
    const float* x  = (const float*)d_in[0];  // (16,192,128) f32
    const float* W  = (const float*)d_in[1];  // (2,1) f32
    const float* bv = (const float*)d_in[2];  // (2,) f32
    float* out = (float*)d_out;               // (16,31898,128) f32

    const int smem = LL * E4 * (int)sizeof(float4);  // 98304 B
    cudaFuncSetAttribute(fused_kernel,
                         cudaFuncAttributeMaxDynamicSharedMemorySize, smem);
    dim3 grid(GX, BB);   // 17 x 16 = 272 CTAs -> one wave at 2 CTA/SM
    fused_kernel<<<grid, TPB, smem>>>(x, W, bv, out);
}

// round 3
// speedup vs baseline: 1.1444x; 1.0529x over previous
#include <cuda_runtime.h>

#define BB 16
#define LL 192
#define EE 128
#define TT 25
#define NI (LL - TT - 1)            // 166
#define OUT_L (TT + 1 + NI * LL)    // 31898
#define E4 (EE / 4)                 // 32 float4 per row
#define I_PER_BLK 19
#define GX ((NI + I_PER_BLK - 1) / I_PER_BLK)  // 9 -> 9*16 = 144 CTAs, 1 wave
#define TPB 512
#define LROWS 16                    // l-groups per pass (TPB/E4)
#define NPASS (LL / LROWS)          // 12

// Precomputed softmax weight s0[b,l,e] (2-way softmax collapsed; s1 = 1-s0).
// 1.5 MB -> L2-resident, read 9x by main kernel.
__device__ float g_s0[BB * LL * EE];

// ---------------------------------------------------------------------------
// Kernel 1: s0 = sigmoid(x*(W0-W1) + (b0-b1))  — the ONLY MUFU in the problem
// ---------------------------------------------------------------------------
__global__ void s0_kernel(const float* __restrict__ x,
                          const float* __restrict__ W,
                          const float* __restrict__ bv) {
    const int N4 = BB * LL * E4;  // 98304
    int n = blockIdx.x * blockDim.x + threadIdx.x;
    if (n >= N4) return;
    float dW = W[0] - W[1];
    float db = bv[0] - bv[1];
    float4 xv = reinterpret_cast<const float4*>(x)[n];
    float4 s;
    s.x = 1.0f / (1.0f + __expf(-fmaf(xv.x, dW, db)));
    s.y = 1.0f / (1.0f + __expf(-fmaf(xv.y, dW, db)));
    s.z = 1.0f / (1.0f + __expf(-fmaf(xv.z, dW, db)));
    s.w = 1.0f / (1.0f + __expf(-fmaf(xv.w, dW, db)));
    reinterpret_cast<float4*>(g_s0)[n] = s;
}

// ---------------------------------------------------------------------------
// Kernel 2 (main): blocks[b,i,l,e] = xp + s0[b,l,e]*(xi-xp)
//   xi = x[b, i+T+1, e], xp = x[b, i+1, e]
// Thread owns fixed (e4, lbase): its 12 s-values are i-invariant -> registers.
// Hot loop: 2 LDG (L1-hit) + 12x(FFMA*4 + STG.128 streaming). No smem/MUFU.
// Warp writes contiguous 512B rows -> fully coalesced.
// ---------------------------------------------------------------------------
__global__ void __launch_bounds__(TPB, 1)
blocks_kernel(const float* __restrict__ x, float* __restrict__ out) {
    const int b = blockIdx.y;
    const int e4    = threadIdx.x & (E4 - 1);   // 0..31, contiguous in warp
    const int lbase = threadIdx.x >> 5;         // 0..15, constant in warp

    const float4* xb = reinterpret_cast<const float4*>(x) + b * (LL * E4);
    const float4* s0b = reinterpret_cast<const float4*>(g_s0) + b * (LL * E4);
    float4* o4 = reinterpret_cast<float4*>(out);

    // Head copy: out[b, 0:26, :] = x[b, 0:26, :]  (done by x==0 CTAs)
    if (blockIdx.x == 0) {
        const size_t ob = (size_t)b * (OUT_L * E4);
        #pragma unroll
        for (int k = threadIdx.x; k < (TT + 1) * E4; k += TPB)
            __stcs(o4 + ob + k, xb[k]);
    }

    // Hoist this thread's 12 s-values into registers (i-invariant)
    float4 s[NPASS];
    #pragma unroll
    for (int p = 0; p < NPASS; p++)
        s[p] = s0b[(lbase + p * LROWS) * E4 + e4];

    const int i0 = blockIdx.x * I_PER_BLK;
    const int iend = min(i0 + I_PER_BLK, NI);

    for (int i = i0; i < iend; i++) {
        float4 xi = xb[(i + TT + 1) * E4 + e4];
        float4 xp = xb[(i + 1) * E4 + e4];
        float4 d;
        d.x = xi.x - xp.x; d.y = xi.y - xp.y;
        d.z = xi.z - xp.z; d.w = xi.w - xp.w;

        size_t obase = ((size_t)b * OUT_L + (TT + 1) + (size_t)i * LL) * E4 + e4;

        #pragma unroll
        for (int p = 0; p < NPASS; p++) {
            float4 o;
            o.x = fmaf(s[p].x, d.x, xp.x);
            o.y = fmaf(s[p].y, d.y, xp.y);
            o.z = fmaf(s[p].z, d.z, xp.z);
            o.w = fmaf(s[p].w, d.w, xp.w);
            // write-once output: streaming store, evict-first in L2
            __stcs(o4 + obase + (size_t)(lbase + p * LROWS) * E4, o);
        }
    }
}

// ---------------------------------------------------------------------------
extern "C" void kernel_launch(void* const* d_in, const int* in_sizes, int n_in,
                              void* d_out, int out_size) {
    const float* x  = (const float*)d_in[0];  // (16,192,128) f32
    const float* W  = (const float*)d_in[1];  // (2,1) f32
    const float* bv = (const float*)d_in[2];  // (2,) f32
    float* out = (float*)d_out;               // (16,31898,128) f32

    const int N4 = BB * LL * E4;
    s0_kernel<<<(N4 + 255) / 256, 256>>>(x, W, bv);

    dim3 grid(GX, BB);   // 9 x 16 = 144 CTAs, single wave
    blocks_kernel<<<grid, TPB>>>(x, out);
}

// round 4
// speedup vs baseline: 1.2161x; 1.0627x over previous
#include <cuda_runtime.h>

#define BB 16
#define LL 192
#define EE 128
#define TT 25
#define NI (LL - TT - 1)            // 166
#define OUT_L (TT + 1 + NI * LL)    // 31898
#define E4 (EE / 4)                 // 32 float4 per row
#define TPB 256
#define WARPS (TPB / 32)            // 8
#define L_RANGE 32                  // l-rows per CTA
#define LSPLITS (LL / L_RANGE)      // 6
#define NPASS (L_RANGE / WARPS)     // 4  -> 16 s-regs/thread
#define I_PER_BLK 12
#define ICH ((NI + I_PER_BLK - 1) / I_PER_BLK)  // 14

// Precomputed softmax weight s0[b,l,e] (2-way softmax collapsed; s1 = 1-s0).
// 1.5 MB -> L2-resident.
__device__ float g_s0[BB * LL * EE];

// ---------------------------------------------------------------------------
// Kernel 1: s0 = sigmoid(x*(W0-W1) + (b0-b1))
// ---------------------------------------------------------------------------
__global__ void s0_kernel(const float* __restrict__ x,
                          const float* __restrict__ W,
                          const float* __restrict__ bv) {
    const int N4 = BB * LL * E4;  // 98304
    int n = blockIdx.x * blockDim.x + threadIdx.x;
    if (n >= N4) return;
    float dW = W[0] - W[1];
    float db = bv[0] - bv[1];
    float4 xv = reinterpret_cast<const float4*>(x)[n];
    float4 s;
    s.x = 1.0f / (1.0f + __expf(-fmaf(xv.x, dW, db)));
    s.y = 1.0f / (1.0f + __expf(-fmaf(xv.y, dW, db)));
    s.z = 1.0f / (1.0f + __expf(-fmaf(xv.z, dW, db)));
    s.w = 1.0f / (1.0f + __expf(-fmaf(xv.w, dW, db)));
    reinterpret_cast<float4*>(g_s0)[n] = s;
}

// ---------------------------------------------------------------------------
// Kernel 2 (main): blocks[b,i,l,e] = xp + s0[b,l,e]*(xi-xp)
//   xi = x[b, i+T+1, e], xp = x[b, i+1, e]
// Grid (ICH, LSPLITS, BB): CTA = (i-chunk, 32 l-rows, batch). 1344 CTAs,
// launch_bounds(256,4) -> 32 warps/SM. Per-thread s state: 4 float4 only.
// Next-i xi/xp prefetched before the store burst (2-stage pipeline).
// Warp writes contiguous 512B rows -> fully coalesced streaming STG.
// ---------------------------------------------------------------------------
__global__ void __launch_bounds__(TPB, 4)
blocks_kernel(const float* __restrict__ x, float* __restrict__ out) {
    const int b  = blockIdx.z;
    const int l0 = blockIdx.y * L_RANGE;
    const int e4 = threadIdx.x & (E4 - 1);     // 0..31, contiguous in warp
    const int w  = threadIdx.x >> 5;           // 0..7, constant in warp

    const float4* xb  = reinterpret_cast<const float4*>(x) + b * (LL * E4);
    const float4* s0b = reinterpret_cast<const float4*>(g_s0) + b * (LL * E4);
    float4* o4 = reinterpret_cast<float4*>(out);

    // Head copy: out[b, 0:26, :] = x[b, 0:26, :] (one CTA per batch)
    if (blockIdx.x == 0 && blockIdx.y == 0) {
        const size_t ob = (size_t)b * (OUT_L * E4);
        #pragma unroll
        for (int k = threadIdx.x; k < (TT + 1) * E4; k += TPB)
            __stcs(o4 + ob + k, xb[k]);
    }

    // Hoist this thread's 4 s-values (i-invariant within CTA)
    float4 s[NPASS];
    #pragma unroll
    for (int p = 0; p < NPASS; p++)
        s[p] = s0b[(l0 + w + p * WARPS) * E4 + e4];

    const int i0 = blockIdx.x * I_PER_BLK;
    const int iend = min(i0 + I_PER_BLK, NI);
    if (i0 >= iend) return;

    // 2-stage pipeline on xi/xp
    float4 xi = xb[(i0 + TT + 1) * E4 + e4];
    float4 xp = xb[(i0 + 1) * E4 + e4];

    for (int i = i0; i < iend; i++) {
        float4 nxi, nxp;
        if (i + 1 < iend) {
            nxi = xb[(i + TT + 2) * E4 + e4];
            nxp = xb[(i + 2) * E4 + e4];
        }

        float4 d;
        d.x = xi.x - xp.x; d.y = xi.y - xp.y;
        d.z = xi.z - xp.z; d.w = xi.w - xp.w;

        size_t obase = ((size_t)b * OUT_L + (TT + 1) + (size_t)i * LL + l0) * E4 + e4;

        #pragma unroll
        for (int p = 0; p < NPASS; p++) {
            float4 o;
            o.x = fmaf(s[p].x, d.x, xp.x);
            o.y = fmaf(s[p].y, d.y, xp.y);
            o.z = fmaf(s[p].z, d.z, xp.z);
            o.w = fmaf(s[p].w, d.w, xp.w);
            __stcs(o4 + obase + (size_t)((w + p * WARPS)) * E4, o);
        }

        xi = nxi; xp = nxp;
    }
}

// ---------------------------------------------------------------------------
extern "C" void kernel_launch(void* const* d_in, const int* in_sizes, int n_in,
                              void* d_out, int out_size) {
    const float* x  = (const float*)d_in[0];  // (16,192,128) f32
    const float* W  = (const float*)d_in[1];  // (2,1) f32
    const float* bv = (const float*)d_in[2];  // (2,) f32
    float* out = (float*)d_out;               // (16,31898,128) f32

    const int N4 = BB * LL * E4;
    s0_kernel<<<(N4 + 255) / 256, 256>>>(x, W, bv);

    dim3 grid(ICH, LSPLITS, BB);   // 14 x 6 x 16 = 1344 CTAs
    blocks_kernel<<<grid, TPB>>>(x, out);
}

// round 5
// speedup vs baseline: 1.2412x; 1.0206x over previous
#include <cuda_runtime.h>

#define BB 16
#define LL 192
#define EE 128
#define TT 25
#define NI (LL - TT - 1)            // 166
#define OUT_L (TT + 1 + NI * LL)    // 31898
#define E4 (EE / 4)                 // 32 float4 per row
#define TPB 256
#define WARPS (TPB / 32)            // 8
#define L_RANGE 16                  // l-rows per CTA
#define LSPLITS (LL / L_RANGE)      // 12
#define NPASS (L_RANGE / WARPS)     // 2  -> 8 s-regs/thread
#define I_PER_BLK 12
#define ICH ((NI + I_PER_BLK - 1) / I_PER_BLK)  // 14

// Precomputed softmax weight s0[b,l,e] (2-way softmax collapsed; s1 = 1-s0).
// 1.5 MB -> L2-resident.
__device__ float g_s0[BB * LL * EE];

// ---------------------------------------------------------------------------
// Kernel 1: s0 = sigmoid(x*(W0-W1) + (b0-b1))
// ---------------------------------------------------------------------------
__global__ void s0_kernel(const float* __restrict__ x,
                          const float* __restrict__ W,
                          const float* __restrict__ bv) {
    const int N4 = BB * LL * E4;  // 98304
    int n = blockIdx.x * blockDim.x + threadIdx.x;
    if (n >= N4) return;
    float dW = W[0] - W[1];
    float db = bv[0] - bv[1];
    float4 xv = reinterpret_cast<const float4*>(x)[n];
    float4 s;
    s.x = 1.0f / (1.0f + __expf(-fmaf(xv.x, dW, db)));
    s.y = 1.0f / (1.0f + __expf(-fmaf(xv.y, dW, db)));
    s.z = 1.0f / (1.0f + __expf(-fmaf(xv.z, dW, db)));
    s.w = 1.0f / (1.0f + __expf(-fmaf(xv.w, dW, db)));
    reinterpret_cast<float4*>(g_s0)[n] = s;
}

// ---------------------------------------------------------------------------
// Kernel 2 (main): blocks[b,i,l,e] = xp + s0[b,l,e]*(xi-xp)
//   xi = x[b, i+T+1, e], xp = x[b, i+1, e]
// Grid (ICH, LSPLITS, BB): CTA = (i-chunk, 16 l-rows, batch). 2688 CTAs.
// launch_bounds(256,6) -> target 48 warps/SM. Per-thread s: 2 float4.
// All hot-loop addresses are pointer increments (no per-i 64-bit mul).
// Warp writes contiguous 512B rows -> fully coalesced streaming STG.
// ---------------------------------------------------------------------------
__global__ void __launch_bounds__(TPB, 6)
blocks_kernel(const float* __restrict__ x, float* __restrict__ out) {
    const int b  = blockIdx.z;
    const int l0 = blockIdx.y * L_RANGE;
    const int e4 = threadIdx.x & (E4 - 1);     // 0..31, contiguous in warp
    const int w  = threadIdx.x >> 5;           // 0..7, constant in warp

    const float4* xb  = reinterpret_cast<const float4*>(x) + b * (LL * E4);
    const float4* s0b = reinterpret_cast<const float4*>(g_s0) + b * (LL * E4);
    float4* o4 = reinterpret_cast<float4*>(out);

    // Head copy: out[b, 0:26, :] = x[b, 0:26, :] (one CTA per batch)
    if (blockIdx.x == 0 && blockIdx.y == 0) {
        const size_t ob = (size_t)b * (OUT_L * E4);
        #pragma unroll
        for (int k = threadIdx.x; k < (TT + 1) * E4; k += TPB)
            __stcs(o4 + ob + k, xb[k]);
    }

    // This thread's 2 s-values (i-invariant within CTA)
    float4 s[NPASS];
    #pragma unroll
    for (int p = 0; p < NPASS; p++)
        s[p] = s0b[(l0 + w + p * WARPS) * E4 + e4];

    const int i0 = blockIdx.x * I_PER_BLK;
    const int iend = min(i0 + I_PER_BLK, NI);
    if (i0 >= iend) return;
    const int n_iter = iend - i0;

    // Hot-loop pointers: advance by constants per i (no per-i multiplies)
    const float4* pxi = xb + (i0 + TT + 1) * E4 + e4;
    const float4* pxp = xb + (i0 + 1) * E4 + e4;
    float4* po = o4 + ((size_t)b * OUT_L + (TT + 1) + (size_t)i0 * LL + l0 + w) * E4 + e4;

    // 2-stage pipeline on xi/xp
    float4 xi = *pxi;
    float4 xp = *pxp;

    for (int it = 0; it < n_iter; it++) {
        float4 nxi, nxp;
        if (it + 1 < n_iter) {
            nxi = pxi[E4];
            nxp = pxp[E4];
        }
        pxi += E4; pxp += E4;

        float4 d;
        d.x = xi.x - xp.x; d.y = xi.y - xp.y;
        d.z = xi.z - xp.z; d.w = xi.w - xp.w;

        #pragma unroll
        for (int p = 0; p < NPASS; p++) {
            float4 o;
            o.x = fmaf(s[p].x, d.x, xp.x);
            o.y = fmaf(s[p].y, d.y, xp.y);
            o.z = fmaf(s[p].z, d.z, xp.z);
            o.w = fmaf(s[p].w, d.w, xp.w);
            // compile-time immediate offset within the pass
            __stcs(po + p * (WARPS * E4), o);
        }
        po += (size_t)(LL * E4);   // next i: advance one L-block

        xi = nxi; xp = nxp;
    }
}

// ---------------------------------------------------------------------------
extern "C" void kernel_launch(void* const* d_in, const int* in_sizes, int n_in,
                              void* d_out, int out_size) {
    const float* x  = (const float*)d_in[0];  // (16,192,128) f32
    const float* W  = (const float*)d_in[1];  // (2,1) f32
    const float* bv = (const float*)d_in[2];  // (2,) f32
    float* out = (float*)d_out;               // (16,31898,128) f32

    const int N4 = BB * LL * E4;
    s0_kernel<<<(N4 + 255) / 256, 256>>>(x, W, bv);

    dim3 grid(ICH, LSPLITS, BB);   // 14 x 12 x 16 = 2688 CTAs
    blocks_kernel<<<grid, TPB>>>(x, out);
}